// round 9
// baseline (speedup 1.0000x reference)
#include <cuda_runtime.h>
#include <cstdint>

// RandomTimeMask: out[n,c,l] = x[n,c,l] if ((l - starts[n,c]) mod L) >= L/4 else 0
// x [128,12,32768] fp32, starts [128,12] int32. L=32768, mask_len=8192.
//
// R9: R7 pacing (1 zero-store + 3 copy vecs per iteration, branch-free) but
// ONE block per row (SPLITS=1). R8 proved MLP isn't binding; remaining rate
// deficit vs R2 attributed to concurrent-DRAM-stream explosion (6144 blocks x
// 7 streams). 1536 blocks x 7 streams restores R2-like stream count and
// longer-lived blocks. App traffic stays at the 336 MB minimum (144R + 192W).

static constexpr int L    = 32768;
static constexpr int ML   = 8192;         // mask_len
static constexpr int LM1  = L - 1;
static constexpr int VPR  = L / 4;        // 8192 float4 per row
static constexpr int VM1  = VPR - 1;      // 8191
static constexpr int THREADS = 256;
static constexpr int JTOT    = 2047;      // paired iterations per row

__global__ __launch_bounds__(THREADS)
void random_time_mask_kernel(const float4* __restrict__ x,
                             const int* __restrict__ starts,
                             float4* __restrict__ out)
{
    const int row = blockIdx.x;                  // 0..1535
    const int s   = __ldg(&starts[row]);         // 0 <= s < L

    const float4* __restrict__ xr = x   + (size_t)row * VPR;
    float4*       __restrict__ yr = out + (size_t)row * VPR;

    const int b0 = s >> 2;                       // first (possibly partial) masked vec
    const int b1 = (b0 + 2048) & VM1;            // vec containing mask end
    const int k0 = (b1 + 1) & VM1;               // kept stream base

    const float4 z = make_float4(0.f, 0.f, 0.f, 0.f);

    // 8 paired iterations per thread; 1 zero store + 3 contiguous-stream copies.
    #pragma unroll 2
    for (int j = threadIdx.x; j < JTOT; j += THREADS) {
        const int mz = (b0 + 1 + j)    & VM1;
        const int c0 = (k0 + j)        & VM1;
        const int c1 = (k0 + 2047 + j) & VM1;
        const int c2 = (k0 + 4094 + j) & VM1;
        const float4 v0 = xr[c0];
        const float4 v1 = xr[c1];
        const float4 v2 = xr[c2];
        yr[mz] = z;
        yr[c0] = v0;
        yr[c1] = v1;
        yr[c2] = v2;
    }

    // Edge vectors (4 per row): boundary vecs b0, b1 (partial mask) and the
    // 2 kept remainder vecs. Full per-lane select path.
    if (threadIdx.x < 4) {
        const int t = threadIdx.x;
        const int v = (t == 0) ? b0
                    : (t == 1) ? b1
                    : (t == 2) ? ((k0 + 6141) & VM1)
                               : ((k0 + 6142) & VM1);
        float4 w = xr[v];
        const int base = v << 2;
        const int o0 = (base     - s) & LM1;
        const int o1 = (base + 1 - s) & LM1;
        const int o2 = (base + 2 - s) & LM1;
        const int o3 = (base + 3 - s) & LM1;
        w.x = (o0 < ML) ? 0.0f : w.x;
        w.y = (o1 < ML) ? 0.0f : w.y;
        w.z = (o2 < ML) ? 0.0f : w.z;
        w.w = (o3 < ML) ? 0.0f : w.w;
        yr[v] = w;
    }
}

extern "C" void kernel_launch(void* const* d_in, const int* in_sizes, int n_in,
                              void* d_out, int out_size)
{
    const float4* x      = (const float4*)d_in[0];
    const int*    starts = (const int*)d_in[1];
    float4*       out    = (float4*)d_out;

    const int n_rows = in_sizes[1];               // 128*12 = 1536
    random_time_mask_kernel<<<n_rows, THREADS>>>(x, starts, out);
}

// round 10
// speedup vs baseline: 1.0773x; 1.0773x over previous
#include <cuda_runtime.h>
#include <cstdint>

// RandomTimeMask: out[n,c,l] = x[n,c,l] if ((l - starts[n,c]) mod L) >= L/4 else 0
// x [128,12,32768] fp32, starts [128,12] int32. L=32768, mask_len=8192.
//
// R10 = R7 (best: paced 1-zero+3-copy body, SPLITS=4) + streaming cache hints
// (.cs: zero reuse, keep dead lines from churning L2) + 1-deep software
// pipeline (next iteration's loads issued before current stores so reads stay
// pending at the controller through each store burst).
// App traffic stays at the 336 MB minimum (144R + 192W).

static constexpr int L    = 32768;
static constexpr int ML   = 8192;         // mask_len
static constexpr int LM1  = L - 1;
static constexpr int VPR  = L / 4;        // 8192 float4 per row
static constexpr int VM1  = VPR - 1;      // 8191
static constexpr int THREADS = 256;
static constexpr int SPLITS  = 4;         // blocks per row
static constexpr int JTOT    = 2047;      // paired iterations per row
static constexpr int JSPAN   = 512;       // per-split span (last split: 511)

__global__ __launch_bounds__(THREADS)
void random_time_mask_kernel(const float4* __restrict__ x,
                             const int* __restrict__ starts,
                             float4* __restrict__ out)
{
    const int row   = blockIdx.x >> 2;           // 0..1535
    const int split = blockIdx.x & 3;            // 0..3
    const int s     = __ldg(&starts[row]);       // 0 <= s < L

    const float4* __restrict__ xr = x   + (size_t)row * VPR;
    float4*       __restrict__ yr = out + (size_t)row * VPR;

    const int b0 = s >> 2;                       // first (possibly partial) masked vec
    const int b1 = (b0 + 2048) & VM1;            // vec containing mask end
    const int k0 = (b1 + 1) & VM1;               // kept stream base

    const float4 z = make_float4(0.f, 0.f, 0.f, 0.f);

    // Two paired iterations per thread, software-pipelined: j1 clamped
    // (duplicate write is idempotent) so the body is branch-free.
    const int j0 = split * JSPAN + threadIdx.x;
    const int j1 = min(j0 + THREADS, JTOT - 1);

    const int mza = (b0 + 1 + j0)    & VM1;
    const int c0a = (k0 + j0)        & VM1;
    const int c1a = (k0 + 2047 + j0) & VM1;
    const int c2a = (k0 + 4094 + j0) & VM1;

    // iteration A loads
    const float4 v0a = __ldcs(&xr[c0a]);
    const float4 v1a = __ldcs(&xr[c1a]);
    const float4 v2a = __ldcs(&xr[c2a]);

    const int mzb = (b0 + 1 + j1)    & VM1;
    const int c0b = (k0 + j1)        & VM1;
    const int c1b = (k0 + 2047 + j1) & VM1;
    const int c2b = (k0 + 4094 + j1) & VM1;

    // iteration B loads issued BEFORE iteration A stores (read-ahead)
    const float4 v0b = __ldcs(&xr[c0b]);
    const float4 v1b = __ldcs(&xr[c1b]);
    const float4 v2b = __ldcs(&xr[c2b]);

    __stcs(&yr[mza], z);
    __stcs(&yr[c0a], v0a);
    __stcs(&yr[c1a], v1a);
    __stcs(&yr[c2a], v2a);

    __stcs(&yr[mzb], z);
    __stcs(&yr[c0b], v0b);
    __stcs(&yr[c1b], v1b);
    __stcs(&yr[c2b], v2b);

    // Edge vectors (4 per row): boundary vecs b0, b1 (partial mask) and the
    // 2 kept remainder vecs. Full per-lane select path.
    if (split == 0 && threadIdx.x < 4) {
        const int t = threadIdx.x;
        const int v = (t == 0) ? b0
                    : (t == 1) ? b1
                    : (t == 2) ? ((k0 + 6141) & VM1)
                               : ((k0 + 6142) & VM1);
        float4 w = xr[v];
        const int base = v << 2;
        const int o0 = (base     - s) & LM1;
        const int o1 = (base + 1 - s) & LM1;
        const int o2 = (base + 2 - s) & LM1;
        const int o3 = (base + 3 - s) & LM1;
        w.x = (o0 < ML) ? 0.0f : w.x;
        w.y = (o1 < ML) ? 0.0f : w.y;
        w.z = (o2 < ML) ? 0.0f : w.z;
        w.w = (o3 < ML) ? 0.0f : w.w;
        yr[v] = w;
    }
}

extern "C" void kernel_launch(void* const* d_in, const int* in_sizes, int n_in,
                              void* d_out, int out_size)
{
    const float4* x      = (const float4*)d_in[0];
    const int*    starts = (const int*)d_in[1];
    float4*       out    = (float4*)d_out;

    const int n_rows = in_sizes[1];               // 128*12 = 1536
    random_time_mask_kernel<<<n_rows * SPLITS, THREADS>>>(x, starts, out);
}

// round 11
// speedup vs baseline: 1.1033x; 1.0241x over previous
#include <cuda_runtime.h>
#include <cstdint>

// RandomTimeMask: out[n,c,l] = x[n,c,l] if ((l - starts[n,c]) mod L) >= L/4 else 0
// x [128,12,32768] fp32, starts [128,12] int32. L=32768, mask_len=8192.
//
// R11 = R10 (paced 1-zero+3-copy, SPLITS=4, .cs hints, read-ahead, clamped
// raggedness) + FULL 128B ALIGNMENT: rows decompose into 256 segments of
// 32 float4 (512B). 63 fully-masked segs -> aligned zero stream; 189 fully-
// kept segs -> 3 aligned copy streams; exactly 4 leftover segs (2 partial +
// 2 kept) via per-lane select. Every warp access is line-aligned (R7-R10
// streams straddled 5 lines/warp -> +25% L1tex wavefronts).

static constexpr int L    = 32768;
static constexpr int ML   = 8192;          // mask_len
static constexpr int LM1  = L - 1;
static constexpr int VPR  = L / 4;         // 8192 float4 per row
static constexpr int VM1  = VPR - 1;       // 8191
static constexpr int THREADS = 256;
static constexpr int SPLITS  = 4;          // blocks per row
static constexpr int JTOT    = 2016;       // 63 segments * 32 vecs
static constexpr int JSPAN   = 512;        // per-split span (last split ragged)

__global__ __launch_bounds__(THREADS)
void random_time_mask_kernel(const float4* __restrict__ x,
                             const int* __restrict__ starts,
                             float4* __restrict__ out)
{
    const int row   = blockIdx.x >> 2;            // 0..1535
    const int split = blockIdx.x & 3;             // 0..3
    const int s     = __ldg(&starts[row]);        // 0 <= s < L

    const float4* __restrict__ xr = x   + (size_t)row * VPR;
    float4*       __restrict__ yr = out + (size_t)row * VPR;

    const int sa = s >> 7;                        // segment (128 elems) holding mask start
    const int za = (sa + 1)  << 5;                // zero-stream base (vec units, aligned)
    const int ca = (sa + 65) << 5;                // copy-stream base (vec units, aligned)

    const float4 z = make_float4(0.f, 0.f, 0.f, 0.f);

    // Two paired iterations per thread; j1 clamped (idempotent duplicate).
    // All bases and split offsets are multiples of 32 -> warp accesses aligned.
    const int j0 = split * JSPAN + threadIdx.x;
    const int j1 = min(j0 + THREADS, JTOT - 1);

    const int mza = (za + j0)        & VM1;
    const int c0a = (ca + j0)        & VM1;
    const int c1a = (ca + 2016 + j0) & VM1;
    const int c2a = (ca + 4032 + j0) & VM1;

    const float4 v0a = __ldcs(&xr[c0a]);
    const float4 v1a = __ldcs(&xr[c1a]);
    const float4 v2a = __ldcs(&xr[c2a]);

    const int mzb = (za + j1)        & VM1;
    const int c0b = (ca + j1)        & VM1;
    const int c1b = (ca + 2016 + j1) & VM1;
    const int c2b = (ca + 4032 + j1) & VM1;

    // read-ahead: iteration B loads before iteration A stores
    const float4 v0b = __ldcs(&xr[c0b]);
    const float4 v1b = __ldcs(&xr[c1b]);
    const float4 v2b = __ldcs(&xr[c2b]);

    __stcs(&yr[mza], z);
    __stcs(&yr[c0a], v0a);
    __stcs(&yr[c1a], v1a);
    __stcs(&yr[c2a], v2a);

    __stcs(&yr[mzb], z);
    __stcs(&yr[c0b], v0b);
    __stcs(&yr[c1b], v1b);
    __stcs(&yr[c2b], v2b);

    // Leftover segments (4 per row): sa and sa+64 (partially masked),
    // sa+254 and sa+255 (fully kept). Per-lane select path, one warp each.
    if (split == 0 && threadIdx.x < 128) {
        const int w    = threadIdx.x >> 5;        // 0..3
        const int lane = threadIdx.x & 31;
        const int seg  = (w == 0) ? sa
                       : (w == 1) ? sa + 64
                       : (w == 2) ? sa + 254
                                  : sa + 255;
        const int v = ((seg << 5) + lane) & VM1;
        float4 t = xr[v];
        const int base = v << 2;
        const int o0 = (base     - s) & LM1;
        const int o1 = (base + 1 - s) & LM1;
        const int o2 = (base + 2 - s) & LM1;
        const int o3 = (base + 3 - s) & LM1;
        t.x = (o0 < ML) ? 0.0f : t.x;
        t.y = (o1 < ML) ? 0.0f : t.y;
        t.z = (o2 < ML) ? 0.0f : t.z;
        t.w = (o3 < ML) ? 0.0f : t.w;
        yr[v] = t;
    }
}

extern "C" void kernel_launch(void* const* d_in, const int* in_sizes, int n_in,
                              void* d_out, int out_size)
{
    const float4* x      = (const float4*)d_in[0];
    const int*    starts = (const int*)d_in[1];
    float4*       out    = (float4*)d_out;

    const int n_rows = in_sizes[1];                // 128*12 = 1536
    random_time_mask_kernel<<<n_rows * SPLITS, THREADS>>>(x, starts, out);
}